// round 5
// baseline (speedup 1.0000x reference)
#include <cuda_runtime.h>
#include <cuda_bf16.h>

// Problem constants (reference shapes are fixed)
#define NN 50000
#define NE 800000
#define IN_CH 64
#define OUT_DIM 128
#define HEADS 4
#define CPH 32           // channels per head
#define NEG 0.2f

// Scratch (static __device__ — allocations are forbidden)
__device__ float g_xt[NN * OUT_DIM];     // transformed features [N,128]  (25.6 MB)
__device__ float g_asrc[NN * HEADS];     // per-node src attention half
__device__ float g_adst[NN * HEADS];     // per-node dst attention half
__device__ float g_esum[NN * HEADS];     // softmax denominators (init w/ self-loop)
__device__ float g_hacc[NN * OUT_DIM];   // message accumulator          (25.6 MB)

__device__ __forceinline__ float lrelu(float v) { return v >= 0.f ? v : NEG * v; }

__device__ __forceinline__ void red_add_v4(float* p, float4 v) {
    asm volatile("red.global.add.v4.f32 [%0], {%1,%2,%3,%4};"
                 :: "l"(p), "f"(v.x), "f"(v.y), "f"(v.z), "f"(v.w) : "memory");
}

__device__ __forceinline__ int clampi(int v, int n) {
    return v < 0 ? 0 : (v >= n ? n - 1 : v);
}

// ---------------------------------------------------------------------------
// Kernel 1: per-node — xt = x @ lin_w^T, attention halves, self-loop esum init
// grid = N, block = 128
// ---------------------------------------------------------------------------
__global__ void __launch_bounds__(128) k_node_prep(
    const float* __restrict__ x, const float* __restrict__ lin_w,
    const float* __restrict__ att_src, const float* __restrict__ att_dst, int N)
{
    int n = blockIdx.x;
    int t = threadIdx.x;
    if (n >= N) return;

    __shared__ float sx[IN_CH];
    if (t < IN_CH) sx[t] = x[n * IN_CH + t];
    __syncthreads();

    const float* w = lin_w + t * IN_CH;
    float acc = 0.f;
#pragma unroll
    for (int k = 0; k < IN_CH; k++) acc += sx[k] * w[k];

    g_xt[n * OUT_DIM + t] = acc;
    g_hacc[n * OUT_DIM + t] = 0.f;

    int h = t >> 5, c = t & 31;
    float as = acc * att_src[h * CPH + c];
    float ad = acc * att_dst[h * CPH + c];
#pragma unroll
    for (int o = 16; o; o >>= 1) {
        as += __shfl_xor_sync(0xFFFFFFFFu, as, o);
        ad += __shfl_xor_sync(0xFFFFFFFFu, ad, o);
    }
    if (c == 0) {
        g_asrc[n * HEADS + h] = as;
        g_adst[n * HEADS + h] = ad;
        // self-loop contribution to softmax denominator
        g_esum[n * HEADS + h] = expf(lrelu(as + ad));
    }
}

// ---------------------------------------------------------------------------
// Kernel 2: per-edge — esum[d] += exp(leaky(a_src[s]+a_dst[d]))   (1 thr/edge)
// edge_index is int32 (JAX silently downcasts int64 without x64 enabled)
// ---------------------------------------------------------------------------
__global__ void __launch_bounds__(256) k_edge_sum(const int* __restrict__ ei, int E, int N)
{
    int e = blockIdx.x * blockDim.x + threadIdx.x;
    if (e >= E) return;
    int s = clampi(ei[e], N);
    int d = clampi(ei[E + e], N);

    float4 as = *reinterpret_cast<const float4*>(g_asrc + s * HEADS);
    float4 ad = *reinterpret_cast<const float4*>(g_adst + d * HEADS);
    float4 ex;
    ex.x = expf(lrelu(as.x + ad.x));
    ex.y = expf(lrelu(as.y + ad.y));
    ex.z = expf(lrelu(as.z + ad.z));
    ex.w = expf(lrelu(as.w + ad.w));
    red_add_v4(g_esum + d * HEADS, ex);
}

// ---------------------------------------------------------------------------
// Kernel 3: per-edge scatter — hacc[d] += xt[s] * alpha   (1 warp / edge)
// alpha recomputed from logits (no per-edge cache needed)
// block = 256 (8 warps), grid = ceil(E/8)
// ---------------------------------------------------------------------------
__global__ void __launch_bounds__(256) k_edge_scatter(const int* __restrict__ ei, int E, int N)
{
    int warp = (blockIdx.x * blockDim.x + threadIdx.x) >> 5;
    int lane = threadIdx.x & 31;
    if (warp >= E) return;
    int s = clampi(ei[warp], N);
    int d = clampi(ei[E + warp], N);

    int h = lane >> 3;  // 8 lanes per head (4 channels each)
    float e  = lrelu(g_asrc[s * HEADS + h] + g_adst[d * HEADS + h]);
    float es = g_esum[d * HEADS + h];
    float alpha = expf(e) / (es + 1e-16f);

    float4 v = *reinterpret_cast<const float4*>(g_xt + s * OUT_DIM + lane * 4);
    v.x *= alpha; v.y *= alpha; v.z *= alpha; v.w *= alpha;
    red_add_v4(g_hacc + d * OUT_DIM + lane * 4, v);
}

// ---------------------------------------------------------------------------
// Kernel 4: per-node finalize — self-loop msg + residual GEMV + LN + LeakyReLU
// grid = N, block = 128
// ---------------------------------------------------------------------------
__global__ void __launch_bounds__(128) k_finalize(
    const float* __restrict__ x, const float* __restrict__ res_w,
    const float* __restrict__ res_b, const float* __restrict__ gat_bias,
    const float* __restrict__ ln_g, const float* __restrict__ ln_b,
    float* __restrict__ out, int N)
{
    int n = blockIdx.x;
    int t = threadIdx.x;
    if (n >= N) return;

    __shared__ float sx[IN_CH];
    __shared__ float sred[4];
    if (t < IN_CH) sx[t] = x[n * IN_CH + t];
    __syncthreads();

    const float* w = res_w + t * IN_CH;
    float r = 0.f;
#pragma unroll
    for (int k = 0; k < IN_CH; k++) r += sx[k] * w[k];

    int h = t >> 5;
    float es = g_esum[n * HEADS + h];
    float e_self = lrelu(g_asrc[n * HEADS + h] + g_adst[n * HEADS + h]);
    float a_self = expf(e_self) / (es + 1e-16f);

    float z = g_hacc[n * OUT_DIM + t]
            + g_xt[n * OUT_DIM + t] * a_self
            + gat_bias[t] + r + res_b[t];

    // block mean over 128
    float sum = z;
#pragma unroll
    for (int o = 16; o; o >>= 1) sum += __shfl_xor_sync(0xFFFFFFFFu, sum, o);
    if ((t & 31) == 0) sred[t >> 5] = sum;
    __syncthreads();
    float mu = (sred[0] + sred[1] + sred[2] + sred[3]) * (1.f / OUT_DIM);

    float zc = z - mu;
    float vv = zc * zc;
#pragma unroll
    for (int o = 16; o; o >>= 1) vv += __shfl_xor_sync(0xFFFFFFFFu, vv, o);
    __syncthreads();            // protect sred reuse
    if ((t & 31) == 0) sred[t >> 5] = vv;
    __syncthreads();
    float var = (sred[0] + sred[1] + sred[2] + sred[3]) * (1.f / OUT_DIM);
    float rs = rsqrtf(var + 1e-5f);

    float zn = zc * rs * ln_g[t] + ln_b[t];
    out[n * OUT_DIM + t] = lrelu(zn);
}

// ---------------------------------------------------------------------------
extern "C" void kernel_launch(void* const* d_in, const int* in_sizes, int n_in,
                              void* d_out, int out_size)
{
    const float* x        = (const float*)d_in[0];
    const int*   ei       = (const int*)d_in[1];     // int32 (JAX x64 disabled)
    const float* lin_w    = (const float*)d_in[2];
    const float* att_src  = (const float*)d_in[3];
    const float* att_dst  = (const float*)d_in[4];
    const float* gat_bias = (const float*)d_in[5];
    const float* res_w    = (const float*)d_in[6];
    const float* res_b    = (const float*)d_in[7];
    const float* ln_g     = (const float*)d_in[8];
    const float* ln_b     = (const float*)d_in[9];
    float* out = (float*)d_out;

    int N = in_sizes[0] / IN_CH;     // 50000
    int E = in_sizes[1] / 2;         // 800000
    if (N > NN) N = NN;              // clamp to static scratch capacity
    if (E > NE) E = NE;

    k_node_prep<<<N, 128>>>(x, lin_w, att_src, att_dst, N);
    k_edge_sum<<<(E + 255) / 256, 256>>>(ei, E, N);
    k_edge_scatter<<<(E + 7) / 8, 256>>>(ei, E, N);
    k_finalize<<<N, 128>>>(x, res_w, res_b, gat_bias, ln_g, ln_b, out, N);
}

// round 6
// speedup vs baseline: 9.9771x; 9.9771x over previous
#include <cuda_runtime.h>
#include <cuda_bf16.h>

// Problem constants (reference shapes are fixed)
#define NN 50000
#define NE 800000
#define IN_CH 64
#define OUT_DIM 128
#define HEADS 4
#define CPH 32           // channels per head
#define NEG 0.2f

// Scratch (static __device__ — allocations are forbidden)
__device__ float g_xt[NN * OUT_DIM];     // transformed features [N,128]  (25.6 MB)
__device__ float g_asrc[NN * HEADS];     // per-node src attention half
__device__ float g_adst[NN * HEADS];     // per-node dst attention half
__device__ float g_esum[NN * HEADS];     // softmax denominators (init w/ self-loop)
__device__ float g_hacc[NN * OUT_DIM];   // message accumulator          (25.6 MB)
__device__ float g_linwT[IN_CH * OUT_DIM];  // lin_w transposed [k][t] — coalesced GEMV
__device__ float g_reswT[IN_CH * OUT_DIM];  // res_w transposed [k][t]

__device__ __forceinline__ float lrelu(float v) { return v >= 0.f ? v : NEG * v; }

__device__ __forceinline__ void red_add_v4(float* p, float4 v) {
    asm volatile("red.global.add.v4.f32 [%0], {%1,%2,%3,%4};"
                 :: "l"(p), "f"(v.x), "f"(v.y), "f"(v.z), "f"(v.w) : "memory");
}

__device__ __forceinline__ int clampi(int v, int n) {
    return v < 0 ? 0 : (v >= n ? n - 1 : v);
}

// ---------------------------------------------------------------------------
// Kernel 0: transpose both weight matrices: wT[k*128+t] = w[t*64+k]
// grid = 64 (one block per k), block = 128
// ---------------------------------------------------------------------------
__global__ void __launch_bounds__(128) k_transpose(
    const float* __restrict__ lin_w, const float* __restrict__ res_w)
{
    int k = blockIdx.x;      // 0..63
    int t = threadIdx.x;     // 0..127
    g_linwT[k * OUT_DIM + t] = lin_w[t * IN_CH + k];
    g_reswT[k * OUT_DIM + t] = res_w[t * IN_CH + k];
}

// ---------------------------------------------------------------------------
// Kernel 1: per-node — xt = x @ lin_w^T, attention halves, self-loop esum init
// grid = N, block = 128. Weight loads now coalesced via g_linwT.
// ---------------------------------------------------------------------------
__global__ void __launch_bounds__(128) k_node_prep(
    const float* __restrict__ x,
    const float* __restrict__ att_src, const float* __restrict__ att_dst, int N)
{
    int n = blockIdx.x;
    int t = threadIdx.x;
    if (n >= N) return;

    __shared__ float sx[IN_CH];
    if (t < IN_CH) sx[t] = x[n * IN_CH + t];
    __syncthreads();

    float acc = 0.f;
#pragma unroll
    for (int k = 0; k < IN_CH; k++) acc += sx[k] * g_linwT[k * OUT_DIM + t];

    g_xt[n * OUT_DIM + t] = acc;
    g_hacc[n * OUT_DIM + t] = 0.f;

    int h = t >> 5, c = t & 31;
    float as = acc * att_src[h * CPH + c];
    float ad = acc * att_dst[h * CPH + c];
#pragma unroll
    for (int o = 16; o; o >>= 1) {
        as += __shfl_xor_sync(0xFFFFFFFFu, as, o);
        ad += __shfl_xor_sync(0xFFFFFFFFu, ad, o);
    }
    if (c == 0) {
        g_asrc[n * HEADS + h] = as;
        g_adst[n * HEADS + h] = ad;
        // self-loop contribution to softmax denominator
        g_esum[n * HEADS + h] = expf(lrelu(as + ad));
    }
}

// ---------------------------------------------------------------------------
// Kernel 2: per-edge — esum[d] += exp(leaky(a_src[s]+a_dst[d]))   (1 thr/edge)
// edge_index is int32 (JAX silently downcasts int64 without x64 enabled)
// ---------------------------------------------------------------------------
__global__ void __launch_bounds__(256) k_edge_sum(const int* __restrict__ ei, int E, int N)
{
    int e = blockIdx.x * blockDim.x + threadIdx.x;
    if (e >= E) return;
    int s = clampi(ei[e], N);
    int d = clampi(ei[E + e], N);

    float4 as = *reinterpret_cast<const float4*>(g_asrc + s * HEADS);
    float4 ad = *reinterpret_cast<const float4*>(g_adst + d * HEADS);
    float4 ex;
    ex.x = expf(lrelu(as.x + ad.x));
    ex.y = expf(lrelu(as.y + ad.y));
    ex.z = expf(lrelu(as.z + ad.z));
    ex.w = expf(lrelu(as.w + ad.w));
    red_add_v4(g_esum + d * HEADS, ex);
}

// ---------------------------------------------------------------------------
// Kernel 3: per-edge scatter — hacc[d] += xt[s] * alpha   (1 warp / edge)
// block = 256 (8 warps), grid = ceil(E/8)
// ---------------------------------------------------------------------------
__global__ void __launch_bounds__(256) k_edge_scatter(const int* __restrict__ ei, int E, int N)
{
    int warp = (blockIdx.x * blockDim.x + threadIdx.x) >> 5;
    int lane = threadIdx.x & 31;
    if (warp >= E) return;
    int s = clampi(ei[warp], N);
    int d = clampi(ei[E + warp], N);

    int h = lane >> 3;  // 8 lanes per head (4 channels each)
    float e  = lrelu(g_asrc[s * HEADS + h] + g_adst[d * HEADS + h]);
    float es = g_esum[d * HEADS + h];
    float alpha = expf(e) / (es + 1e-16f);

    float4 v = *reinterpret_cast<const float4*>(g_xt + s * OUT_DIM + lane * 4);
    v.x *= alpha; v.y *= alpha; v.z *= alpha; v.w *= alpha;
    red_add_v4(g_hacc + d * OUT_DIM + lane * 4, v);
}

// ---------------------------------------------------------------------------
// Kernel 4: per-node finalize — self-loop msg + residual GEMV + LN + LeakyReLU
// grid = N, block = 128. Weight loads now coalesced via g_reswT.
// ---------------------------------------------------------------------------
__global__ void __launch_bounds__(128) k_finalize(
    const float* __restrict__ x,
    const float* __restrict__ res_b, const float* __restrict__ gat_bias,
    const float* __restrict__ ln_g, const float* __restrict__ ln_b,
    float* __restrict__ out, int N)
{
    int n = blockIdx.x;
    int t = threadIdx.x;
    if (n >= N) return;

    __shared__ float sx[IN_CH];
    __shared__ float sred[4];
    if (t < IN_CH) sx[t] = x[n * IN_CH + t];
    __syncthreads();

    float r = 0.f;
#pragma unroll
    for (int k = 0; k < IN_CH; k++) r += sx[k] * g_reswT[k * OUT_DIM + t];

    int h = t >> 5;
    float es = g_esum[n * HEADS + h];
    float e_self = lrelu(g_asrc[n * HEADS + h] + g_adst[n * HEADS + h]);
    float a_self = expf(e_self) / (es + 1e-16f);

    float z = g_hacc[n * OUT_DIM + t]
            + g_xt[n * OUT_DIM + t] * a_self
            + gat_bias[t] + r + res_b[t];

    // block mean over 128
    float sum = z;
#pragma unroll
    for (int o = 16; o; o >>= 1) sum += __shfl_xor_sync(0xFFFFFFFFu, sum, o);
    if ((t & 31) == 0) sred[t >> 5] = sum;
    __syncthreads();
    float mu = (sred[0] + sred[1] + sred[2] + sred[3]) * (1.f / OUT_DIM);

    float zc = z - mu;
    float vv = zc * zc;
#pragma unroll
    for (int o = 16; o; o >>= 1) vv += __shfl_xor_sync(0xFFFFFFFFu, vv, o);
    __syncthreads();            // protect sred reuse
    if ((t & 31) == 0) sred[t >> 5] = vv;
    __syncthreads();
    float var = (sred[0] + sred[1] + sred[2] + sred[3]) * (1.f / OUT_DIM);
    float rs = rsqrtf(var + 1e-5f);

    float zn = zc * rs * ln_g[t] + ln_b[t];
    out[n * OUT_DIM + t] = lrelu(zn);
}

// ---------------------------------------------------------------------------
extern "C" void kernel_launch(void* const* d_in, const int* in_sizes, int n_in,
                              void* d_out, int out_size)
{
    const float* x        = (const float*)d_in[0];
    const int*   ei       = (const int*)d_in[1];     // int32 (JAX x64 disabled)
    const float* lin_w    = (const float*)d_in[2];
    const float* att_src  = (const float*)d_in[3];
    const float* att_dst  = (const float*)d_in[4];
    const float* gat_bias = (const float*)d_in[5];
    const float* res_w    = (const float*)d_in[6];
    const float* res_b    = (const float*)d_in[7];
    const float* ln_g     = (const float*)d_in[8];
    const float* ln_b     = (const float*)d_in[9];
    float* out = (float*)d_out;

    int N = in_sizes[0] / IN_CH;     // 50000
    int E = in_sizes[1] / 2;         // 800000
    if (N > NN) N = NN;              // clamp to static scratch capacity
    if (E > NE) E = NE;

    k_transpose<<<IN_CH, 128>>>(lin_w, res_w);
    k_node_prep<<<N, 128>>>(x, att_src, att_dst, N);
    k_edge_sum<<<(E + 255) / 256, 256>>>(ei, E, N);
    k_edge_scatter<<<(E + 7) / 8, 256>>>(ei, E, N);
    k_finalize<<<N, 128>>>(x, res_b, gat_bias, ln_g, ln_b, out, N);
}

// round 7
// speedup vs baseline: 10.5296x; 1.0554x over previous
#include <cuda_runtime.h>
#include <cuda_bf16.h>

// Problem constants (reference shapes are fixed)
#define NN 50000
#define NE 800000
#define IN_CH 64
#define OUT_DIM 128
#define HEADS 4
#define CPH 32           // channels per head
#define NEG 0.2f

// Scratch (static __device__ — allocations are forbidden)
__device__ float g_xt[NN * OUT_DIM];        // transformed features [N,128] (25.6 MB)
__device__ float g_asrc[NN * HEADS];        // per-node src attention half
__device__ float g_adst[NN * HEADS];        // per-node dst attention half
__device__ float g_linwT[IN_CH * OUT_DIM];  // lin_w transposed [k][t]
__device__ float g_reswT[IN_CH * OUT_DIM];  // res_w transposed [k][t]
__device__ int   g_deg[NN];                 // in-degree per dst
__device__ int   g_rowptr[NN];              // CSR row start
__device__ int   g_cursor[NN];              // fill cursor (== row end after fill)
__device__ int   g_srcs[NE];                // CSR column (source node ids)

__device__ __forceinline__ float lrelu(float v) { return v >= 0.f ? v : NEG * v; }
__device__ __forceinline__ int clampi(int v, int n) {
    return v < 0 ? 0 : (v >= n ? n - 1 : v);
}

// ---------------------------------------------------------------------------
// Kernel 0: transpose weights + zero degree counters
// grid = 64, block = 128
// ---------------------------------------------------------------------------
__global__ void __launch_bounds__(128) k_transpose(
    const float* __restrict__ lin_w, const float* __restrict__ res_w, int N)
{
    int k = blockIdx.x;      // 0..63
    int t = threadIdx.x;     // 0..127
    g_linwT[k * OUT_DIM + t] = lin_w[t * IN_CH + k];
    g_reswT[k * OUT_DIM + t] = res_w[t * IN_CH + k];
    for (int i = blockIdx.x * 128 + t; i < N; i += 64 * 128) g_deg[i] = 0;
}

// ---------------------------------------------------------------------------
// Kernel 1: per-node — xt = x @ lin_w^T, attention halves
// grid = N, block = 128
// ---------------------------------------------------------------------------
__global__ void __launch_bounds__(128) k_node_prep(
    const float* __restrict__ x,
    const float* __restrict__ att_src, const float* __restrict__ att_dst, int N)
{
    int n = blockIdx.x;
    int t = threadIdx.x;
    if (n >= N) return;

    __shared__ float sx[IN_CH];
    if (t < IN_CH) sx[t] = x[n * IN_CH + t];
    __syncthreads();

    float acc = 0.f;
#pragma unroll
    for (int k = 0; k < IN_CH; k++) acc += sx[k] * g_linwT[k * OUT_DIM + t];

    g_xt[n * OUT_DIM + t] = acc;

    int h = t >> 5, c = t & 31;
    float as = acc * att_src[h * CPH + c];
    float ad = acc * att_dst[h * CPH + c];
#pragma unroll
    for (int o = 16; o; o >>= 1) {
        as += __shfl_xor_sync(0xFFFFFFFFu, as, o);
        ad += __shfl_xor_sync(0xFFFFFFFFu, ad, o);
    }
    if (c == 0) {
        g_asrc[n * HEADS + h] = as;
        g_adst[n * HEADS + h] = ad;
    }
}

// ---------------------------------------------------------------------------
// Kernel 2: count in-degrees
// ---------------------------------------------------------------------------
__global__ void __launch_bounds__(256) k_count(const int* __restrict__ ei, int E, int N)
{
    int e = blockIdx.x * blockDim.x + threadIdx.x;
    if (e >= E) return;
    int d = clampi(ei[E + e], N);
    atomicAdd(&g_deg[d], 1);
}

// ---------------------------------------------------------------------------
// Kernel 3: exclusive prefix scan of degrees (single block, 1024 threads)
// ---------------------------------------------------------------------------
__global__ void __launch_bounds__(1024) k_scan(int N)
{
    __shared__ int ts[1024];
    int t = threadIdx.x;
    int chunk = (N + 1023) / 1024;
    int lo = t * chunk;
    int hi = lo + chunk; if (hi > N) hi = N;

    int s = 0;
    for (int i = lo; i < hi; i++) s += g_deg[i];
    ts[t] = s;
    __syncthreads();

    // inclusive Hillis-Steele over thread sums
    for (int off = 1; off < 1024; off <<= 1) {
        int v = (t >= off) ? ts[t - off] : 0;
        __syncthreads();
        ts[t] += v;
        __syncthreads();
    }
    int run = ts[t] - s;   // exclusive prefix for this thread's chunk
    for (int i = lo; i < hi; i++) {
        g_rowptr[i] = run;
        g_cursor[i] = run;
        run += g_deg[i];
    }
}

// ---------------------------------------------------------------------------
// Kernel 4: fill CSR columns
// ---------------------------------------------------------------------------
__global__ void __launch_bounds__(256) k_fill(const int* __restrict__ ei, int E, int N)
{
    int e = blockIdx.x * blockDim.x + threadIdx.x;
    if (e >= E) return;
    int s = clampi(ei[e], N);
    int d = clampi(ei[E + e], N);
    int p = atomicAdd(&g_cursor[d], 1);
    g_srcs[p] = s;
}

// ---------------------------------------------------------------------------
// Kernel 5: one warp per dst node — softmax denom, weighted aggregate,
// self-loop, residual GEMV, LayerNorm, LeakyReLU, store. No atomics, no hacc.
// block = 256 (8 warps = 8 nodes), grid = ceil(N/8)
// ---------------------------------------------------------------------------
__global__ void __launch_bounds__(256) k_aggregate(
    const float* __restrict__ x,
    const float* __restrict__ res_b, const float* __restrict__ gat_bias,
    const float* __restrict__ ln_g, const float* __restrict__ ln_b,
    float* __restrict__ out, int N)
{
    int w    = threadIdx.x >> 5;
    int lane = threadIdx.x & 31;
    int d = blockIdx.x * 8 + w;
    if (d >= N) return;

    int r0 = g_rowptr[d];
    int r1 = g_cursor[d];          // == row end after fill

    int hA = lane & 3;             // pass-A head (4 heads x 8 edges per iter)
    int hB = lane >> 3;            // pass-B head (lane*4 channels -> head)

    float adst_hA = g_adst[d * HEADS + hA];
    float asrc_d  = g_asrc[d * HEADS + hA];

    // ---- pass A: softmax denominator (8 edges per warp-iteration) ----
    float acc_e = 0.f;
    for (int base = r0; base < r1; base += 8) {
        int e = base + (lane >> 2);
        if (e < r1) {
            int s = g_srcs[e];
            acc_e += expf(lrelu(g_asrc[s * HEADS + hA] + adst_hA));
        }
    }
    acc_e += __shfl_xor_sync(0xFFFFFFFFu, acc_e, 4);
    acc_e += __shfl_xor_sync(0xFFFFFFFFu, acc_e, 8);
    acc_e += __shfl_xor_sync(0xFFFFFFFFu, acc_e, 16);

    float ex_self = expf(lrelu(asrc_d + adst_hA));
    float esum_hA = acc_e + ex_self;     // lanes 0..3 hold heads 0..3

    float esum_B   = __shfl_sync(0xFFFFFFFFu, esum_hA, hB);
    float adst_hB  = __shfl_sync(0xFFFFFFFFu, adst_hA, hB);
    float exself_B = __shfl_sync(0xFFFFFFFFu, ex_self, hB);
    float inv_es = 1.f / (esum_B + 1e-16f);

    // ---- pass B: weighted aggregation (1 edge per warp-iteration) ----
    float4 acc = make_float4(0.f, 0.f, 0.f, 0.f);
    for (int e = r0; e < r1; e++) {
        int s = g_srcs[e];
        float alpha = expf(lrelu(g_asrc[s * HEADS + hB] + adst_hB)) * inv_es;
        float4 v = *reinterpret_cast<const float4*>(g_xt + s * OUT_DIM + lane * 4);
        acc.x += v.x * alpha; acc.y += v.y * alpha;
        acc.z += v.z * alpha; acc.w += v.w * alpha;
    }
    // self-loop
    {
        float alpha = exself_B * inv_es;
        float4 v = *reinterpret_cast<const float4*>(g_xt + d * OUT_DIM + lane * 4);
        acc.x += v.x * alpha; acc.y += v.y * alpha;
        acc.z += v.z * alpha; acc.w += v.w * alpha;
    }

    // ---- residual GEMV (per-warp smem x row, coalesced transposed weights) ----
    __shared__ float sx[8][IN_CH];
    sx[w][lane]      = x[d * IN_CH + lane];
    sx[w][lane + 32] = x[d * IN_CH + lane + 32];
    __syncwarp();

    float4 r = make_float4(0.f, 0.f, 0.f, 0.f);
#pragma unroll
    for (int k = 0; k < IN_CH; k++) {
        float xv = sx[w][k];
        float4 wv = *reinterpret_cast<const float4*>(g_reswT + k * OUT_DIM + lane * 4);
        r.x += xv * wv.x; r.y += xv * wv.y; r.z += xv * wv.z; r.w += xv * wv.w;
    }

    int t0 = lane * 4;
    float4 gb  = *reinterpret_cast<const float4*>(gat_bias + t0);
    float4 rb  = *reinterpret_cast<const float4*>(res_b + t0);
    float4 z;
    z.x = acc.x + gb.x + r.x + rb.x;
    z.y = acc.y + gb.y + r.y + rb.y;
    z.z = acc.z + gb.z + r.z + rb.z;
    z.w = acc.w + gb.w + r.w + rb.w;

    // ---- LayerNorm over 128 (warp reduce) ----
    float sum = z.x + z.y + z.z + z.w;
#pragma unroll
    for (int o = 16; o; o >>= 1) sum += __shfl_xor_sync(0xFFFFFFFFu, sum, o);
    float mu = sum * (1.f / OUT_DIM);

    float4 zc;
    zc.x = z.x - mu; zc.y = z.y - mu; zc.z = z.z - mu; zc.w = z.w - mu;
    float vv = zc.x * zc.x + zc.y * zc.y + zc.z * zc.z + zc.w * zc.w;
#pragma unroll
    for (int o = 16; o; o >>= 1) vv += __shfl_xor_sync(0xFFFFFFFFu, vv, o);
    float rs = rsqrtf(vv * (1.f / OUT_DIM) + 1e-5f);

    float4 lg = *reinterpret_cast<const float4*>(ln_g + t0);
    float4 lb = *reinterpret_cast<const float4*>(ln_b + t0);
    float4 o4;
    o4.x = lrelu(zc.x * rs * lg.x + lb.x);
    o4.y = lrelu(zc.y * rs * lg.y + lb.y);
    o4.z = lrelu(zc.z * rs * lg.z + lb.z);
    o4.w = lrelu(zc.w * rs * lg.w + lb.w);
    *reinterpret_cast<float4*>(out + d * OUT_DIM + t0) = o4;
}

// ---------------------------------------------------------------------------
extern "C" void kernel_launch(void* const* d_in, const int* in_sizes, int n_in,
                              void* d_out, int out_size)
{
    const float* x        = (const float*)d_in[0];
    const int*   ei       = (const int*)d_in[1];     // int32 (JAX x64 disabled)
    const float* lin_w    = (const float*)d_in[2];
    const float* att_src  = (const float*)d_in[3];
    const float* att_dst  = (const float*)d_in[4];
    const float* gat_bias = (const float*)d_in[5];
    const float* res_w    = (const float*)d_in[6];
    const float* res_b    = (const float*)d_in[7];
    const float* ln_g     = (const float*)d_in[8];
    const float* ln_b     = (const float*)d_in[9];
    float* out = (float*)d_out;

    int N = in_sizes[0] / IN_CH;     // 50000
    int E = in_sizes[1] / 2;         // 800000
    if (N > NN) N = NN;              // clamp to static scratch capacity
    if (E > NE) E = NE;

    k_transpose<<<IN_CH, 128>>>(lin_w, res_w, N);
    k_node_prep<<<N, 128>>>(x, att_src, att_dst, N);
    k_count<<<(E + 255) / 256, 256>>>(ei, E, N);
    k_scan<<<1, 1024>>>(N);
    k_fill<<<(E + 255) / 256, 256>>>(ei, E, N);
    k_aggregate<<<(N + 7) / 8, 256>>>(x, res_b, gat_bias, ln_g, ln_b, out, N);
}